// round 13
// baseline (speedup 1.0000x reference)
#include <cuda_runtime.h>
#include <cuda_fp16.h>
#include <cstdint>

#define NB 4
#define CG 9
#define DD 16
#define DCELLS (DD*DD*DD)       // 4096 cells
#define HWSZ (1024*1024)
#define GRID_X 111
#define CTAS_TOTAL (GRID_X * NB)   // 444 = 148 SMs x 3 CTAs
#define CELLS_PER_CTA ((DCELLS + GRID_X - 1) / GRID_X)   // 37

// Packed projected grid: per entry (r,g,b): 6 halves = channels {0,1,2} of cell b
// followed by channels {0,1,2} of cell b+1, padded to 16B. 256KB scratch.
__device__ uint4 d_pgrid[NB * DCELLS];

// Arrival / exit counters for the in-kernel grid barrier. Reset by the last
// CTA out each launch, so every launch sees them at 0.
__device__ int g_arrive;
__device__ int g_depart;

struct F3 { float x, y, z; };

__device__ __forceinline__ F3 unpack_lerp_b(uint4 e, float fb) {
    float2 p0 = __half22float2(*(const __half2*)&e.x);   // c0(b), c1(b)
    float2 p1 = __half22float2(*(const __half2*)&e.y);   // c2(b), c0(b+1)
    float2 p2 = __half22float2(*(const __half2*)&e.z);   // c1(b+1), c2(b+1)
    F3 r;
    r.x = fmaf(fb, p1.y - p0.x, p0.x);
    r.y = fmaf(fb, p2.x - p0.y, p0.y);
    r.z = fmaf(fb, p2.y - p1.x, p1.x);
    return r;
}

__device__ __forceinline__ F3 lerp3(F3 a, F3 b, float t) {
    F3 r;
    r.x = fmaf(t, b.x - a.x, a.x);
    r.y = fmaf(t, b.y - a.y, a.y);
    r.z = fmaf(t, b.z - a.z, a.z);
    return r;
}

__global__ __launch_bounds__(256, 3) void slice_conv_kernel(
    const float* __restrict__ grid,
    const float* __restrict__ guide,
    const float* __restrict__ cw,
    const float* __restrict__ cb,
    float* __restrict__ out)
{
    extern __shared__ uint4 sg[];   // 4096 * 16B = 64 KB
    const int n = blockIdx.y;

    const float4* gR = (const float4*)(guide + (size_t)(n * 3 + 0) * HWSZ);
    const float4* gG = (const float4*)(guide + (size_t)(n * 3 + 1) * HWSZ);
    const float4* gB = (const float4*)(guide + (size_t)(n * 3 + 2) * HWSZ);
    float4* oR = (float4*)(out + (size_t)(n * 3 + 0) * HWSZ);
    float4* oG = (float4*)(out + (size_t)(n * 3 + 1) * HWSZ);
    float4* oB = (float4*)(out + (size_t)(n * 3 + 2) * HWSZ);

    const int nq     = HWSZ / 4;
    const int stride = gridDim.x * blockDim.x;
    int q = blockIdx.x * blockDim.x + threadIdx.x;

    // --- Prime the guide pipeline (independent of projection/table).
    float4 r4, g4, b4;
    bool live = (q < nq);
    if (live) {
        r4 = __ldcs(gR + q);
        g4 = __ldcs(gG + q);
        b4 = __ldcs(gB + q);
    }

    // --- Distributed projection: this CTA projects CELLS_PER_CTA cells of
    //     image n through conv_w[:, :9] into d_pgrid (b-pair fp16 entries).
    {
        int cell = blockIdx.x * CELLS_PER_CTA + threadIdx.x;   // 37 active threads
        if (threadIdx.x < CELLS_PER_CTA && cell < DCELLS) {
            const float* g0 = grid + (size_t)n * CG * DCELLS + cell;
            int hoff = ((cell & 15) == 15) ? 0 : 1;   // b=15 hi-half never read

            float lo0 = 0.f, lo1 = 0.f, lo2 = 0.f;
            float hi0 = 0.f, hi1 = 0.f, hi2 = 0.f;
#pragma unroll
            for (int c = 0; c < CG; c++) {
                float vl = g0[c * DCELLS];
                float vh = g0[c * DCELLS + hoff];
                float w0 = cw[0 * 12 + c], w1 = cw[1 * 12 + c], w2 = cw[2 * 12 + c];
                lo0 = fmaf(w0, vl, lo0); lo1 = fmaf(w1, vl, lo1); lo2 = fmaf(w2, vl, lo2);
                hi0 = fmaf(w0, vh, hi0); hi1 = fmaf(w1, vh, hi1); hi2 = fmaf(w2, vh, hi2);
            }

            __half2 h01 = __floats2half2_rn(lo0, lo1);
            __half2 h23 = __floats2half2_rn(lo2, hi0);
            __half2 h45 = __floats2half2_rn(hi1, hi2);
            uint4 e;
            e.x = *(const unsigned int*)&h01;
            e.y = *(const unsigned int*)&h23;
            e.z = *(const unsigned int*)&h45;
            e.w = 0u;
            d_pgrid[(n << 12) + cell] = e;
        }
    }

    // --- Grid barrier: all 444 CTAs are co-resident (148 SMs x 3), so a
    //     spin barrier is safe. Arrive after our stores are visible.
    __threadfence();
    __syncthreads();
    if (threadIdx.x == 0) {
        atomicAdd(&g_arrive, 1);
        while (atomicAdd(&g_arrive, 0) < CTAS_TOTAL) { }
    }
    __syncthreads();   // releases whole CTA; also orders table reads after poll

    // --- Stage the full 64KB table for image n into smem.
    {
        const uint4* pg = d_pgrid + (n << 12);
        for (int i = threadIdx.x; i < DCELLS; i += blockDim.x) sg[i] = pg[i];
    }
    __syncthreads();

    const float wr9 = cw[ 9], wr10 = cw[10], wr11 = cw[11], br = cb[0];
    const float wg9 = cw[21], wg10 = cw[22], wg11 = cw[23], bg = cb[1];
    const float wb9 = cw[33], wb10 = cw[34], wb11 = cw[35], bb = cb[2];

    if (live) {
        while (q < nq) {
            int qn = q + stride;
            float4 rn, gn, bn;
            if (qn < nq) {
                rn = __ldcs(gR + qn);
                gn = __ldcs(gG + qn);
                bn = __ldcs(gB + qn);
            }

            float4 or4, og4, ob4;
            const float* rr = (const float*)&r4;
            const float* gg = (const float*)&g4;
            const float* bv = (const float*)&b4;
            float* po0 = (float*)&or4;
            float* po1 = (float*)&og4;
            float* po2 = (float*)&ob4;

#pragma unroll
            for (int e = 0; e < 4; e++) {
                float r = rr[e], g = gg[e], b = bv[e];

                float crd = __saturatef(r) * 15.f;
                float cgd = __saturatef(g) * 15.f;
                float cbd = __saturatef(b) * 15.f;
                int ir = (int)crd; ir = ir > 14 ? 14 : ir;
                int ig = (int)cgd; ig = ig > 14 ? 14 : ig;
                int ib = (int)cbd; ib = ib > 14 ? 14 : ib;
                float fr = crd - (float)ir;
                float fg = cgd - (float)ig;
                float fb = cbd - (float)ib;

                int base = ir * 256 + ig * 16 + ib;

                uint4 e00 = sg[base];
                uint4 e01 = sg[base +  16];
                uint4 e10 = sg[base + 256];
                uint4 e11 = sg[base + 272];

                F3 c00 = unpack_lerp_b(e00, fb);
                F3 c01 = unpack_lerp_b(e01, fb);
                F3 c10 = unpack_lerp_b(e10, fb);
                F3 c11 = unpack_lerp_b(e11, fb);
                F3 c0  = lerp3(c00, c01, fg);
                F3 c1  = lerp3(c10, c11, fg);
                F3 cc  = lerp3(c0, c1, fr);

                po0[e] = fmaf(wr11, b, fmaf(wr10, g, fmaf(wr9, r, cc.x + br)));
                po1[e] = fmaf(wg11, b, fmaf(wg10, g, fmaf(wg9, r, cc.y + bg)));
                po2[e] = fmaf(wb11, b, fmaf(wb10, g, fmaf(wb9, r, cc.z + bb)));
            }

            __stcs(oR + q, or4);
            __stcs(oG + q, og4);
            __stcs(oB + q, ob4);

            q = qn;
            r4 = rn; g4 = gn; b4 = bn;
        }
    }

    // --- Exit protocol: last CTA out resets both counters for the next launch.
    __syncthreads();
    if (threadIdx.x == 0) {
        int d = atomicAdd(&g_depart, 1);
        if (d == CTAS_TOTAL - 1) {
            atomicExch(&g_arrive, 0);
            atomicExch(&g_depart, 0);
        }
    }
}

// ---------------------------------------------------------------------------
// Launch: single kernel.
// ---------------------------------------------------------------------------
extern "C" void kernel_launch(void* const* d_in, const int* in_sizes, int n_in,
                              void* d_out, int out_size) {
    const float* grid  = (const float*)d_in[0];   // (4,9,16,16,16)
    const float* guide = (const float*)d_in[1];   // (4,3,1024,1024)
    const float* cw    = (const float*)d_in[2];   // (3,12)
    const float* cb    = (const float*)d_in[3];   // (3,)
    float* out = (float*)d_out;                   // (4,3,1024,1024)

    cudaFuncSetAttribute(slice_conv_kernel,
                         cudaFuncAttributeMaxDynamicSharedMemorySize, 65536);

    dim3 blocks(GRID_X, NB);   // 444 CTAs = 148 SMs x 3 CTAs/SM (64KB smem each)
    slice_conv_kernel<<<blocks, 256, 65536>>>(grid, guide, cw, cb, out);
}

// round 14
// speedup vs baseline: 1.0495x; 1.0495x over previous
#include <cuda_runtime.h>
#include <cuda_fp16.h>
#include <cstdint>

#define NB 4
#define CG 9
#define DD 16
#define DCELLS (DD*DD*DD)       // 4096 cells
#define HWSZ (1024*1024)
#define TABLE_BYTES (DCELLS * 16)   // 64 KB

// Packed projected grid: per entry (r,g,b): 6 halves = channels {0,1,2} of cell b
// followed by channels {0,1,2} of cell b+1, padded to 16B. 4 * 4096 * 16B = 256KB.
__device__ uint4 d_pgrid[NB * DCELLS];

// ---------------------------------------------------------------------------
// Kernel 1: project 9-channel grid through conv_w[:, :9] -> packed fp16 pairs.
// Coalesced: thread == cell; b+1 neighbor via shfl (lanes 15/31 hold b=15
// cells whose hi-halves are never read, since ib <= 14).
// ---------------------------------------------------------------------------
__global__ void project_grid_kernel(const float* __restrict__ grid,
                                    const float* __restrict__ cw) {
    int idx = blockIdx.x * blockDim.x + threadIdx.x;
    if (idx >= NB * DCELLS) return;
    int n    = idx >> 12;       // / 4096
    int cell = idx & 4095;      // r*256 + g*16 + b

    const float* g0 = grid + (size_t)n * CG * DCELLS + cell;

    float a0 = 0.f, a1 = 0.f, a2 = 0.f;
#pragma unroll
    for (int c = 0; c < CG; c++) {
        float v = g0[c * DCELLS];
        a0 = fmaf(cw[0 * 12 + c], v, a0);
        a1 = fmaf(cw[1 * 12 + c], v, a1);
        a2 = fmaf(cw[2 * 12 + c], v, a2);
    }

    float h0 = __shfl_down_sync(0xFFFFFFFFu, a0, 1);
    float h1 = __shfl_down_sync(0xFFFFFFFFu, a1, 1);
    float h2 = __shfl_down_sync(0xFFFFFFFFu, a2, 1);

    __half2 h01 = __floats2half2_rn(a0, a1);   // (c0(b),  c1(b))
    __half2 h23 = __floats2half2_rn(a2, h0);   // (c2(b),  c0(b+1))
    __half2 h45 = __floats2half2_rn(h1, h2);   // (c1(b+1),c2(b+1))

    uint4 e;
    e.x = *(const unsigned int*)&h01;
    e.y = *(const unsigned int*)&h23;
    e.z = *(const unsigned int*)&h45;
    e.w = 0u;
    d_pgrid[idx] = e;
}

// ---------------------------------------------------------------------------
// Kernel 2: fused slice + conv. 64KB b-pair table bulk-copied into smem via
// cp.async.bulk + mbarrier; 4x LDS.128/pixel; 512 threads, 2 CTAs/SM
// (32 warps/SM — first test of high occupancy WITH the good layout+pipeline).
// ---------------------------------------------------------------------------
struct F3 { float x, y, z; };

__device__ __forceinline__ uint32_t smem_u32(const void* p) {
    uint32_t a;
    asm("{ .reg .u64 t; cvta.to.shared.u64 t, %1; cvt.u32.u64 %0, t; }"
        : "=r"(a) : "l"(p));
    return a;
}

__device__ __forceinline__ F3 unpack_lerp_b(uint4 e, float fb) {
    float2 p0 = __half22float2(*(const __half2*)&e.x);   // c0(b), c1(b)
    float2 p1 = __half22float2(*(const __half2*)&e.y);   // c2(b), c0(b+1)
    float2 p2 = __half22float2(*(const __half2*)&e.z);   // c1(b+1), c2(b+1)
    F3 r;
    r.x = fmaf(fb, p1.y - p0.x, p0.x);
    r.y = fmaf(fb, p2.x - p0.y, p0.y);
    r.z = fmaf(fb, p2.y - p1.x, p1.x);
    return r;
}

__device__ __forceinline__ F3 lerp3(F3 a, F3 b, float t) {
    F3 r;
    r.x = fmaf(t, b.x - a.x, a.x);
    r.y = fmaf(t, b.y - a.y, a.y);
    r.z = fmaf(t, b.z - a.z, a.z);
    return r;
}

__global__ __launch_bounds__(512, 2) void slice_conv_kernel(
    const float* __restrict__ guide,
    const float* __restrict__ cw,
    const float* __restrict__ cb,
    float* __restrict__ out)
{
    extern __shared__ uint4 sg[];            // 4096 * 16B = 64 KB
    __shared__ alignas(8) uint64_t mbar;
    const int n = blockIdx.y;

    const float4* gR = (const float4*)(guide + (size_t)(n * 3 + 0) * HWSZ);
    const float4* gG = (const float4*)(guide + (size_t)(n * 3 + 1) * HWSZ);
    const float4* gB = (const float4*)(guide + (size_t)(n * 3 + 2) * HWSZ);
    float4* oR = (float4*)(out + (size_t)(n * 3 + 0) * HWSZ);
    float4* oG = (float4*)(out + (size_t)(n * 3 + 1) * HWSZ);
    float4* oB = (float4*)(out + (size_t)(n * 3 + 2) * HWSZ);

    const int nq     = HWSZ / 4;
    const int stride = gridDim.x * blockDim.x;
    int q = blockIdx.x * blockDim.x + threadIdx.x;

    // Prime the guide pipeline first (DRAM latency overlaps the bulk copy).
    float4 r4, g4, b4;
    bool live = (q < nq);
    if (live) {
        r4 = __ldcs(gR + q);
        g4 = __ldcs(gG + q);
        b4 = __ldcs(gB + q);
    }

    // Bulk-async stage the 64KB table.
    uint32_t mb = smem_u32(&mbar);
    if (threadIdx.x == 0) {
        asm volatile("mbarrier.init.shared.b64 [%0], %1;" :: "r"(mb), "r"(1) : "memory");
    }
    __syncthreads();
    if (threadIdx.x == 0) {
        uint32_t dst = smem_u32(sg);
        const void* src = (const void*)(d_pgrid + n * DCELLS);
        asm volatile("mbarrier.arrive.expect_tx.shared.b64 _, [%0], %1;"
                     :: "r"(mb), "r"((uint32_t)TABLE_BYTES) : "memory");
        asm volatile("cp.async.bulk.shared::cluster.global.mbarrier::complete_tx::bytes "
                     "[%0], [%1], %2, [%3];"
                     :: "r"(dst), "l"(src), "r"((uint32_t)TABLE_BYTES), "r"(mb)
                     : "memory");
    }
    // All threads wait for the copy (acquire orders subsequent LDS).
    {
        uint32_t done = 0;
        while (!done) {
            asm volatile(
                "{\n\t.reg .pred p;\n\t"
                "mbarrier.try_wait.parity.acquire.cta.shared::cta.b64 p, [%1], %2, 0x989680;\n\t"
                "selp.b32 %0, 1, 0, p;\n\t}"
                : "=r"(done) : "r"(mb), "r"(0u) : "memory");
        }
    }

    if (!live) return;

    const float wr9 = cw[ 9], wr10 = cw[10], wr11 = cw[11], br = cb[0];
    const float wg9 = cw[21], wg10 = cw[22], wg11 = cw[23], bg = cb[1];
    const float wb9 = cw[33], wb10 = cw[34], wb11 = cw[35], bb = cb[2];

    while (q < nq) {
        int qn = q + stride;
        float4 rn, gn, bn;
        if (qn < nq) {
            rn = __ldcs(gR + qn);
            gn = __ldcs(gG + qn);
            bn = __ldcs(gB + qn);
        }

        float4 or4, og4, ob4;
        const float* rr = (const float*)&r4;
        const float* gg = (const float*)&g4;
        const float* bv = (const float*)&b4;
        float* po0 = (float*)&or4;
        float* po1 = (float*)&og4;
        float* po2 = (float*)&ob4;

#pragma unroll
        for (int e = 0; e < 4; e++) {
            float r = rr[e], g = gg[e], b = bv[e];

            float crd = __saturatef(r) * 15.f;
            float cgd = __saturatef(g) * 15.f;
            float cbd = __saturatef(b) * 15.f;
            int ir = (int)crd; ir = ir > 14 ? 14 : ir;
            int ig = (int)cgd; ig = ig > 14 ? 14 : ig;
            int ib = (int)cbd; ib = ib > 14 ? 14 : ib;
            float fr = crd - (float)ir;
            float fg = cgd - (float)ig;
            float fb = cbd - (float)ib;

            int base = ir * 256 + ig * 16 + ib;

            uint4 e00 = sg[base];
            uint4 e01 = sg[base +  16];
            uint4 e10 = sg[base + 256];
            uint4 e11 = sg[base + 272];

            F3 c00 = unpack_lerp_b(e00, fb);
            F3 c01 = unpack_lerp_b(e01, fb);
            F3 c10 = unpack_lerp_b(e10, fb);
            F3 c11 = unpack_lerp_b(e11, fb);
            F3 c0  = lerp3(c00, c01, fg);
            F3 c1  = lerp3(c10, c11, fg);
            F3 cc  = lerp3(c0, c1, fr);

            po0[e] = fmaf(wr11, b, fmaf(wr10, g, fmaf(wr9, r, cc.x + br)));
            po1[e] = fmaf(wg11, b, fmaf(wg10, g, fmaf(wg9, r, cc.y + bg)));
            po2[e] = fmaf(wb11, b, fmaf(wb10, g, fmaf(wb9, r, cc.z + bb)));
        }

        __stcs(oR + q, or4);
        __stcs(oG + q, og4);
        __stcs(oB + q, ob4);

        q = qn;
        r4 = rn; g4 = gn; b4 = bn;
    }
}

// ---------------------------------------------------------------------------
// Launch
// ---------------------------------------------------------------------------
extern "C" void kernel_launch(void* const* d_in, const int* in_sizes, int n_in,
                              void* d_out, int out_size) {
    const float* grid  = (const float*)d_in[0];   // (4,9,16,16,16)
    const float* guide = (const float*)d_in[1];   // (4,3,1024,1024)
    const float* cw    = (const float*)d_in[2];   // (3,12)
    const float* cb    = (const float*)d_in[3];   // (3,)
    float* out = (float*)d_out;                   // (4,3,1024,1024)

    cudaFuncSetAttribute(slice_conv_kernel,
                         cudaFuncAttributeMaxDynamicSharedMemorySize, 65536);

    project_grid_kernel<<<(NB * DCELLS + 255) / 256, 256>>>(grid, cw);

    dim3 blocks(74, NB);   // 296 CTAs = 148 SMs x 2 CTAs/SM (64KB smem each)
    slice_conv_kernel<<<blocks, 512, 65536>>>(guide, cw, cb, out);
}